// round 16
// baseline (speedup 1.0000x reference)
#include <cuda_runtime.h>
#include <cuda_fp16.h>
#include <math.h>
#include <stdint.h>

// ---- problem constants ----
#define NWIN 98
#define NH 3
#define HD 32
#define CD 96
#define DD 16
#define HH 112
#define WW2 112
#define NWX 2048
#define BATCH 2
#define BTOT (BATCH*NWX)      // 4096
#define MTOT (BTOT*NWIN)      // 401408
#define LTOT (DD*HH*WW2)      // 200704
#define SCALE 0.17677669529663689f
#define LOG2E 1.4426950408889634f

// ---- scratch (fp16 intermediates) ----
__device__ __half g_q[(size_t)BTOT*NH*NWIN*HD];   // q pre-scaled by SCALE*LOG2E
__device__ __half g_k[(size_t)BTOT*NH*NWIN*HD];
__device__ __half g_v[(size_t)BTOT*NH*NWIN*HD];
__device__ __half g_ao[(size_t)MTOT*CD];
__device__ __half g_y[(size_t)MTOT*CD];          // windowed-linear order
__device__ __half g_Bp[5*9216];                  // prepacked fp16 B frags
// bias+mask prepacked in per-thread fragment order:
// [(cls*3+head)*7 + warp][j=nt*2+rr][lane]  (lane-minor -> coalesced)
#define BMP_TOTAL (24 * 7 * 26 * 32)             // 139776 words
__device__ unsigned g_bmP[BMP_TOTAL];

// ---- helpers ----
__device__ __forceinline__ unsigned pack_h2(float a, float b) {
    __half2 h = __floats2half2_rn(a, b);
    return *(unsigned*)&h;
}
__device__ __forceinline__ float ex2f(float x) {
    float r;
    asm("ex2.approx.ftz.f32 %0, %1;" : "=f"(r) : "f"(x));
    return r;
}
__device__ __forceinline__ void cp16(unsigned saddr, const void* gptr) {
    asm volatile("cp.async.cg.shared.global [%0], [%1], 16;"
        :: "r"(saddr), "l"(gptr));
}
#define CP_COMMIT() asm volatile("cp.async.commit_group;" ::: "memory")
#define CP_WAIT0()  asm volatile("cp.async.wait_group 0;" ::: "memory")
__device__ __forceinline__ void mma_f16(float* d, unsigned a0, unsigned a1,
                                        unsigned a2, unsigned a3,
                                        unsigned b0, unsigned b1) {
    asm volatile(
        "mma.sync.aligned.m16n8k16.row.col.f32.f16.f16.f32 "
        "{%0,%1,%2,%3}, {%4,%5,%6,%7}, {%8,%9}, {%0,%1,%2,%3};"
        : "+f"(d[0]), "+f"(d[1]), "+f"(d[2]), "+f"(d[3])
        : "r"(a0), "r"(a1), "r"(a2), "r"(a3), "r"(b0), "r"(b1));
}
__device__ __forceinline__ void ldsm_x4_trans(unsigned& r0, unsigned& r1,
                                              unsigned& r2, unsigned& r3,
                                              unsigned addr) {
    asm volatile("ldmatrix.sync.aligned.m8n8.x4.trans.shared.b16 {%0,%1,%2,%3}, [%4];"
        : "=r"(r0), "=r"(r1), "=r"(r2), "=r"(r3) : "r"(addr));
}

// ---- bias+mask scalar (device) ----
__device__ __forceinline__ float bm_val(const float* table, const float* mask,
                                        int cls, int head, int n, int m) {
    int d1 = n / 49, h1 = (n % 49) / 7, w1 = n % 7;
    int d2 = m / 49, h2 = (m % 49) / 7, w2 = m % 7;
    int t = (d1 - d2 + 1) * 169 + (h1 - h2 + 6) * 13 + (w1 - w2 + 6);
    int wd = (cls & 4) ? 7 : 0;
    int wh = (cls & 2) ? 15 : 0;
    int ww = (cls & 1) ? 15 : 0;
    int widx = wd * 256 + wh * 16 + ww;
    return (table[t * NH + head] + mask[(size_t)widx * (NWIN * NWIN) + n * NWIN + m]) * LOG2E;
}

// ============ K0: bmP table + weight prepack ============
__global__ void init_kernel(const float* __restrict__ table,
                            const float* __restrict__ mask,
                            const float* __restrict__ qkvw,
                            const float* __restrict__ projw,
                            const float* __restrict__ fc1w) {
    int idx = blockIdx.x * blockDim.x + threadIdx.x;
    if (idx < BMP_TOTAL) {
        int lane = idx & 31;
        int q1 = idx >> 5;
        int j = q1 % 26;
        int cw = q1 / 26;
        int w = cw % 7;
        int ch = cw / 7;
        int cls = ch / NH, head = ch % NH;
        int g = lane >> 2, tig = lane & 3;
        int nt = j >> 1, rr = j & 1;
        int row = w * 16 + g + rr * 8;
        int c0 = nt * 8 + tig * 2;
        unsigned v = 0u;
        if (row < 98 && c0 < 98) {
            float b0 = bm_val(table, mask, cls, head, row, c0);
            float b1 = bm_val(table, mask, cls, head, row, c0 + 1);
            v = pack_h2(b0, b1);
        }
        g_bmP[idx] = v;
    } else if (idx < BMP_TOTAL + 5 * 9216) {
        int p = idx - BMP_TOTAL;
        int mat = p / 9216, rem = p % 9216;
        int c = rem / 96, k = rem % 96;
        float v;
        if (mat < 3) v = qkvw[(size_t)(mat * 96 + c) * 96 + k];
        else if (mat == 3) v = projw[(size_t)c * 96 + k];
        else v = fc1w[(size_t)c * 96 + k];
        int nt = c >> 3, g = c & 7, kt = k >> 4, w16 = k & 15;
        int reg = w16 >> 3, tig = (w16 & 7) >> 1, lo = w16 & 1;
        int hidx = ((((nt * 6 + kt) * 32) + g * 4 + tig) * 2 + reg) * 2 + lo;
        g_Bp[mat * 9216 + hidx] = __float2half_rn(v);
    }
}

// ============ GEMM common ============
#define QKV_SMEM ((6656 + 2 * 4608) * 4)
#define TC_SMEM  ((6656 + 4608 + 128) * 4)

__device__ __forceinline__ void mma6(float d[12][4], const unsigned* sAw,
                                     const unsigned* sB, int r0, int tig, int lane) {
    const uint2* b2 = (const uint2*)sB;
    #pragma unroll
    for (int kt = 0; kt < 6; kt++) {
        unsigned a0 = sAw[r0 * 52 + kt * 8 + tig];
        unsigned a1 = sAw[(r0 + 8) * 52 + kt * 8 + tig];
        unsigned a2 = sAw[r0 * 52 + kt * 8 + tig + 4];
        unsigned a3 = sAw[(r0 + 8) * 52 + kt * 8 + tig + 4];
        #pragma unroll
        for (int nt = 0; nt < 12; nt++) {
            uint2 bf = b2[(nt * 6 + kt) * 32 + lane];
            mma_f16(d[nt], a0, a1, a2, a3, bf.x, bf.y);
        }
    }
}

// ============ K1: fused LayerNorm + window-partition + QKV GEMM ============
__global__ __launch_bounds__(256, 3)
void gemm_qkv(const float* __restrict__ x,
              const float* __restrict__ nw,
              const float* __restrict__ nb,
              const float* __restrict__ bias) {
    extern __shared__ unsigned smu[];
    unsigned* sAw = smu;
    __half* sAh = (__half*)smu;
    unsigned* sB0 = smu + 6656;
    unsigned* sB1 = smu + 6656 + 4608;
    int rowbase = blockIdx.x * 128;
    int tid = threadIdx.x;
    int w = tid >> 5, lane = tid & 31;
    int g = lane >> 2, tig = lane & 3;

    {
        unsigned sb0a = (unsigned)__cvta_generic_to_shared(sB0);
        const uint4* s4 = (const uint4*)g_Bp;
        for (int i = tid; i < 1152; i += 256) cp16(sb0a + i * 16, s4 + i);
        CP_COMMIT();
    }

    float nw0 = nw[lane], nw1 = nw[lane + 32], nw2 = nw[lane + 64];
    float nb0 = nb[lane], nb1 = nb[lane + 32], nb2 = nb[lane + 64];

    #pragma unroll 4
    for (int i = 0; i < 16; i++) {
        int r = w * 16 + i;
        int m = rowbase + r;
        int b_ = m / NWIN, n = m % NWIN;
        int b = b_ >> 11;
        int widx = b_ & (NWX - 1);
        int wd = widx >> 8, wh = (widx >> 4) & 15, ww = widx & 15;
        int nd = n / 49, nr = n % 49, nh2 = nr / 7, nw2i = nr % 7;
        int dp = wd * 2 + nd, hp = wh * 7 + nh2, wp = ww * 7 + nw2i;
        int d = dp + 1; if (d >= DD) d -= DD;
        int h = hp + 3; if (h >= HH) h -= HH;
        int wq = wp + 3; if (wq >= WW2) wq -= WW2;
        size_t src = ((size_t)b * LTOT + (size_t)(d * (HH * WW2) + h * WW2 + wq)) * CD;
        float v0 = x[src + lane], v1 = x[src + 32 + lane], v2 = x[src + 64 + lane];
        float s = v0 + v1 + v2;
        float ss = v0 * v0 + v1 * v1 + v2 * v2;
        #pragma unroll
        for (int o = 16; o; o >>= 1) {
            s  += __shfl_xor_sync(0xffffffffu, s, o);
            ss += __shfl_xor_sync(0xffffffffu, ss, o);
        }
        float mean = s * (1.0f / 96.0f);
        float var = ss * (1.0f / 96.0f) - mean * mean;
        float rs = rsqrtf(var + 1e-5f);
        sAh[r * 104 + lane]      = __float2half_rn((v0 - mean) * rs * nw0 + nb0);
        sAh[r * 104 + lane + 32] = __float2half_rn((v1 - mean) * rs * nw1 + nb1);
        sAh[r * 104 + lane + 64] = __float2half_rn((v2 - mean) * rs * nw2 + nb2);
    }

    int m0 = rowbase + w * 16 + g;
    int b0 = m0 / NWIN, n0 = m0 % NWIN;
    int b1 = (m0 + 8) / NWIN, n1 = (m0 + 8) % NWIN;
    int r0 = w * 16 + g;
    CP_WAIT0();
    __syncthreads();

    #pragma unroll
    for (int p = 0; p < 3; p++) {
        unsigned* bufs[2] = { sB0, sB1 };
        if (p < 2) {
            unsigned nba = (unsigned)__cvta_generic_to_shared(bufs[(p + 1) & 1]);
            const uint4* s4 = (const uint4*)(g_Bp + (size_t)(p + 1) * 9216);
            for (int i = tid; i < 1152; i += 256) cp16(nba + i * 16, s4 + i);
            CP_COMMIT();
        }
        float d[12][4];
        #pragma unroll
        for (int nt = 0; nt < 12; nt++)
            #pragma unroll
            for (int r = 0; r < 4; r++) d[nt][r] = 0.0f;
        mma6(d, sAw, bufs[p & 1], r0, tig, lane);

        __half* dstbuf = (p == 0) ? g_q : (p == 1) ? g_k : g_v;
        float sc = (p == 0) ? (SCALE * LOG2E) : 1.0f;
        #pragma unroll
        for (int nt = 0; nt < 12; nt++) {
            int c = nt * 8 + tig * 2;
            int head = c >> 5, wd = c & 31;
            float bx = bias[p * 96 + c], by = bias[p * 96 + c + 1];
            *(unsigned*)(dstbuf + ((((size_t)b0 * NH + head) * NWIN + n0) * HD + wd)) =
                pack_h2((d[nt][0] + bx) * sc, (d[nt][1] + by) * sc);
            *(unsigned*)(dstbuf + ((((size_t)b1 * NH + head) * NWIN + n1) * HD + wd)) =
                pack_h2((d[nt][2] + bx) * sc, (d[nt][3] + by) * sc);
        }
        if (p < 2) {
            CP_WAIT0();
            __syncthreads();
        }
    }
}

// ============ proj (EPI=1): linear store / fc1 (EPI=2): gather + GELU + resid ============
template<int EPI>
__global__ __launch_bounds__(256, 3)
void gemm_tc(const float* __restrict__ bias,
             const float* __restrict__ resid,
             float* __restrict__ out) {
    extern __shared__ unsigned smu[];
    unsigned* sAw = smu;
    unsigned* sB = smu + 6656;
    int* rowmap = (int*)(smu + 11264);
    int rowbase = blockIdx.x * 128;
    int tid = threadIdx.x;
    int w = tid >> 5, lane = tid & 31;
    int g = lane >> 2, tig = lane & 3;
    int r0 = w * 16 + g;
    unsigned sAa = (unsigned)__cvta_generic_to_shared(sAw);
    unsigned sBa = (unsigned)__cvta_generic_to_shared(sB);

    if (EPI == 2) {
        if (tid < 128) {
            int m = rowbase + tid;
            int b = m / LTOT;
            int l = m - b * LTOT;
            int d = l / (HH * WW2);
            int rem = l - d * (HH * WW2);
            int h = rem / WW2;
            int w2 = rem - h * WW2;
            int dp = d - 1; if (dp < 0) dp += DD;
            int hp = h - 3; if (hp < 0) hp += HH;
            int wp = w2 - 3; if (wp < 0) wp += WW2;
            int wd = dp >> 1, nd = dp & 1;
            int wh = hp / 7, nh = hp - wh * 7;
            int ww = wp / 7, nww = wp - ww * 7;
            rowmap[tid] = ((b << 11) + wd * 256 + wh * 16 + ww) * 98 +
                          nd * 49 + nh * 7 + nww;
        }
        __syncthreads();
        const uint4* A4 = (const uint4*)g_y;
        #pragma unroll
        for (int it = 0; it < 6; it++) {
            int idx = tid + it * 256;
            int r = idx / 12, k8 = idx % 12;
            cp16(sAa + (r * 52 + k8 * 4) * 4, A4 + (size_t)rowmap[r] * 12 + k8);
        }
    } else {
        const uint4* A4 = (const uint4*)(g_ao + (size_t)rowbase * 96);
        #pragma unroll
        for (int it = 0; it < 6; it++) {
            int idx = tid + it * 256;
            int r = idx / 12, k8 = idx % 12;
            cp16(sAa + (r * 52 + k8 * 4) * 4, A4 + idx);
        }
    }
    {
        const uint4* s4 = (const uint4*)(g_Bp + (size_t)(EPI == 1 ? 3 : 4) * 9216);
        for (int i = tid; i < 1152; i += 256) cp16(sBa + i * 16, s4 + i);
    }
    CP_COMMIT();
    CP_WAIT0();
    __syncthreads();

    float d[12][4];
    #pragma unroll
    for (int nt = 0; nt < 12; nt++)
        #pragma unroll
        for (int r = 0; r < 4; r++) d[nt][r] = 0.0f;
    mma6(d, sAw, sB, r0, tig, lane);

    int m0 = rowbase + r0;
    if (EPI == 1) {
        #pragma unroll
        for (int nt = 0; nt < 12; nt++) {
            int c = nt * 8 + tig * 2;
            float bx = bias[c], by = bias[c + 1];
            *(unsigned*)(g_y + (size_t)m0 * CD + c) = pack_h2(d[nt][0] + bx, d[nt][1] + by);
            *(unsigned*)(g_y + (size_t)(m0 + 8) * CD + c) = pack_h2(d[nt][2] + bx, d[nt][3] + by);
        }
    } else {
        #pragma unroll
        for (int nt = 0; nt < 12; nt++) {
            int c = nt * 8 + tig * 2;
            float bx = bias[c], by = bias[c + 1];
            #pragma unroll
            for (int rr = 0; rr < 2; rr++) {
                size_t o = (size_t)(m0 + rr * 8) * CD + c;
                float v0 = d[nt][rr * 2] + bx;
                float v1 = d[nt][rr * 2 + 1] + by;
                float g0 = 0.5f * v0 * (1.0f + erff(v0 * 0.70710678118654752f));
                float g1 = 0.5f * v1 * (1.0f + erff(v1 * 0.70710678118654752f));
                float2 rv = *(const float2*)(resid + o);
                *(float2*)(out + o) = make_float2(rv.x + g0, rv.y + g1);
            }
        }
    }
}

// ============ K3: fp16-MMA window attention — register-resident P, coalesced bm ============
// smem (u32 words): q_h [112][20] 2240 @0, k_h [104][20] 2080 @2240,
//                   vs [112][20] 2240 @4320  -> 6560 words = 26240 B
#define ATTN_SMEM (6560 * 4)
__global__ __launch_bounds__(224, 4)
void attn_kernel() {
    extern __shared__ unsigned smu[];
    unsigned* q_h = smu;
    unsigned* k_h = smu + 2240;
    unsigned* vs = smu + 4320;

    int b_ = blockIdx.x;
    int head = blockIdx.y;
    int tid = threadIdx.x;
    int w = tid >> 5, lane = tid & 31;
    int g = lane >> 2, tig = lane & 3;
    size_t bh = (size_t)b_ * NH + head;

    // ---- cp.async loads ----
    {
        unsigned qa = (unsigned)__cvta_generic_to_shared(q_h);
        unsigned ka = (unsigned)__cvta_generic_to_shared(k_h);
        unsigned va = (unsigned)__cvta_generic_to_shared(vs);
        const uint4* q4 = (const uint4*)(g_q + bh * (NWIN * HD));
        const uint4* k4 = (const uint4*)(g_k + bh * (NWIN * HD));
        const uint4* v4 = (const uint4*)(g_v + bh * (NWIN * HD));
        for (int i4 = tid; i4 < 392; i4 += 224) {
            int n = i4 >> 2, c4 = (i4 & 3) << 2;
            unsigned off = (n * 20 + c4) * 4;
            cp16(qa + off, q4 + i4);
            cp16(ka + off, k4 + i4);
            cp16(va + off, v4 + i4);
        }
        CP_COMMIT();
        {
            int n = 98 + (tid >> 4), ww2 = tid & 15;
            vs[n * 20 + ww2] = 0u;
        }
        CP_WAIT0();
    }
    __syncthreads();   // the ONLY block barrier

    int r0 = w * 16 + g;
    // ---- S = Q K^T ----
    float d[13][4];
    #pragma unroll
    for (int nt = 0; nt < 13; nt++)
        #pragma unroll
        for (int r = 0; r < 4; r++) d[nt][r] = 0.0f;
    {
        unsigned a[2][4];
        #pragma unroll
        for (int kt = 0; kt < 2; kt++) {
            a[kt][0] = q_h[r0 * 20 + kt * 8 + tig];
            a[kt][1] = q_h[(r0 + 8) * 20 + kt * 8 + tig];
            a[kt][2] = q_h[r0 * 20 + kt * 8 + tig + 4];
            a[kt][3] = q_h[(r0 + 8) * 20 + kt * 8 + tig + 4];
        }
        #pragma unroll
        for (int nt = 0; nt < 13; nt++) {
            #pragma unroll
            for (int kt = 0; kt < 2; kt++) {
                unsigned b0 = k_h[(nt * 8 + g) * 20 + kt * 8 + tig];
                unsigned b1 = k_h[(nt * 8 + g) * 20 + kt * 8 + tig + 4];
                mma_f16(d[nt], a[kt][0], a[kt][1], a[kt][2], a[kt][3], b0, b1);
            }
        }
    }

    bool v0 = r0 < 98, v1 = (r0 + 8) < 98;
    // ---- softmax in registers; coalesced per-thread bm loads ----
    unsigned pa[13][2];
    {
        int widx = b_ & (NWX - 1);
        int cls = (((widx >> 8) == 7) << 2) | ((((widx >> 4) & 15) == 15) << 1) |
                  ((widx & 15) == 15);
        const unsigned* bmp = g_bmP +
            (((size_t)(cls * NH + head) * 7 + w) * 26) * 32 + lane;
        float s0 = 0.0f, s1 = 0.0f;
        #pragma unroll
        for (int nt = 0; nt < 13; nt++) {
            int c0 = nt * 8 + tig * 2;
            float e0 = 0.f, e1 = 0.f, e2 = 0.f, e3 = 0.f;
            if (c0 < 98) {
                unsigned bw0 = __ldg(bmp + (nt * 2) * 32);
                float2 bb0 = __half22float2(*(__half2*)&bw0);
                e0 = ex2f(d[nt][0] + bb0.x);
                e1 = ex2f(d[nt][1] + bb0.y);
                unsigned bw1 = __ldg(bmp + (nt * 2 + 1) * 32);
                float2 bb1 = __half22float2(*(__half2*)&bw1);
                e2 = ex2f(d[nt][2] + bb1.x);
                e3 = ex2f(d[nt][3] + bb1.y);
            }
            d[nt][0] = e0; d[nt][1] = e1; d[nt][2] = e2; d[nt][3] = e3;
            s0 += e0 + e1; s1 += e2 + e3;
        }
        s0 += __shfl_xor_sync(0xffffffffu, s0, 1);
        s0 += __shfl_xor_sync(0xffffffffu, s0, 2);
        s1 += __shfl_xor_sync(0xffffffffu, s1, 1);
        s1 += __shfl_xor_sync(0xffffffffu, s1, 2);
        float i0 = 1.0f / s0;
        float i1 = 1.0f / s1;
        #pragma unroll
        for (int nt = 0; nt < 13; nt++) {
            pa[nt][0] = pack_h2(d[nt][0] * i0, d[nt][1] * i0);
            pa[nt][1] = pack_h2(d[nt][2] * i1, d[nt][3] * i1);
        }
    }

    // ---- O = P V ----
    {
        unsigned vs_addr = (unsigned)__cvta_generic_to_shared(vs);
        int sub = lane & 7, hsel = (lane >> 3) & 1, nsel = lane >> 4;
        float o[4][4];
        #pragma unroll
        for (int nt = 0; nt < 4; nt++)
            #pragma unroll
            for (int r = 0; r < 4; r++) o[nt][r] = 0.0f;
        #pragma unroll
        for (int kt = 0; kt < 7; kt++) {
            unsigned a0 = pa[2 * kt][0];
            unsigned a1 = pa[2 * kt][1];
            unsigned a2 = (kt < 6) ? pa[2 * kt + 1][0] : 0u;
            unsigned a3 = (kt < 6) ? pa[2 * kt + 1][1] : 0u;
            #pragma unroll
            for (int ntp = 0; ntp < 2; ntp++) {
                unsigned addr = vs_addr +
                    ((unsigned)((16 * kt + 8 * hsel + sub) * 40 +
                                8 * (ntp * 2 + nsel)) << 1);
                unsigned b0, b1, b2, b3;
                ldsm_x4_trans(b0, b1, b2, b3, addr);
                mma_f16(o[ntp * 2], a0, a1, a2, a3, b0, b1);
                mma_f16(o[ntp * 2 + 1], a0, a1, a2, a3, b2, b3);
            }
        }
        #pragma unroll
        for (int nt = 0; nt < 4; nt++) {
            int c = nt * 8 + tig * 2;
            if (v0)
                *(unsigned*)(g_ao + ((size_t)b_ * NWIN + r0) * CD + head * HD + c) =
                    pack_h2(o[nt][0], o[nt][1]);
            if (v1)
                *(unsigned*)(g_ao + ((size_t)b_ * NWIN + r0 + 8) * CD + head * HD + c) =
                    pack_h2(o[nt][2], o[nt][3]);
        }
    }
}

// ============ launch ============
extern "C" void kernel_launch(void* const* d_in, const int* in_sizes, int n_in,
                              void* d_out, int out_size) {
    const float* x     = (const float*)d_in[0];
    const float* mask  = (const float*)d_in[1];
    const float* n1w   = (const float*)d_in[2];
    const float* n1b   = (const float*)d_in[3];
    const float* qkvw  = (const float*)d_in[4];
    const float* qkvb  = (const float*)d_in[5];
    const float* relt  = (const float*)d_in[6];
    const float* projw = (const float*)d_in[7];
    const float* projb = (const float*)d_in[8];
    const float* fc1w  = (const float*)d_in[9];
    const float* fc1b  = (const float*)d_in[10];
    float* out = (float*)d_out;

    cudaFuncSetAttribute(attn_kernel, cudaFuncAttributeMaxDynamicSharedMemorySize, ATTN_SMEM);
    cudaFuncSetAttribute(gemm_qkv, cudaFuncAttributeMaxDynamicSharedMemorySize, QKV_SMEM);
    cudaFuncSetAttribute(gemm_tc<1>, cudaFuncAttributeMaxDynamicSharedMemorySize, TC_SMEM);
    cudaFuncSetAttribute(gemm_tc<2>, cudaFuncAttributeMaxDynamicSharedMemorySize, TC_SMEM);

    init_kernel<<<(BMP_TOTAL + 5 * 9216 + 255) / 256, 256>>>(relt, mask, qkvw, projw, fc1w);
    gemm_qkv<<<MTOT / 128, 256, QKV_SMEM>>>(x, n1w, n1b, qkvb);
    attn_kernel<<<dim3(BTOT, NH), 224, ATTN_SMEM>>>();
    gemm_tc<1><<<MTOT / 128, 256, TC_SMEM>>>(projb, nullptr, nullptr);
    gemm_tc<2><<<MTOT / 128, 256, TC_SMEM>>>(fc1b, x, out);
}